// round 13
// baseline (speedup 1.0000x reference)
#include <cuda_runtime.h>
#include <cuda_bf16.h>

// MedSegNetV2: 3x3 texture features + martingale — register-rolling march.
// One warp = one full 224-wide row (28 lanes x 8 px), marching down a 16-row
// chunk of one plane. 3-row window in a register ring; no smem, no barriers.
// R13: occupancy 5->6 blocks/SM, contrast as min/max clamp, running out ptr.
// x: [8,64,224,224] f32 -> out: [8,256,224,224] f32, channel = c*4 + feature.

#define IMG_H 224
#define IMG_W 224
#define PLANE (IMG_H * IMG_W)
#define CH 16
#define CHUNKS (IMG_H / CH)       // 14
#define PL0 (-1.3815511e-5f)      // 1e-6 * ln(1e-6)

#define MC   0.6065306597126334f          // exp(-0.5)
#define K1   ((8.0f / 9.0f) * MC)         // contrast ceiling (= value at threshold)
#define KC0  (MC / 9e-6f)                 // contrast tiny-variance slope
#define KE   (MC / 9.0f)
#define KH   (9.0f * MC)

#define FETCH(y) do {                                                         \
    if ((unsigned)(y) < IMG_H) {                                              \
        fa = *(const float4*)(base + (size_t)(y) * IMG_W);                    \
        fb = *(const float4*)(base + (size_t)(y) * IMG_W + 4);                \
    } else {                                                                  \
        fa = make_float4(0.f, 0.f, 0.f, 0.f);                                 \
        fb = make_float4(0.f, 0.f, 0.f, 0.f);                                 \
    }                                                                         \
} while (0)

// Consume fa/fb (one image row) into ring slot s: raw values + plogp tri-sums.
#define ROWPROC(s) do {                                                       \
    float nl = __shfl_up_sync(FULL, fb.w, 1);   if (L0)  nl = 0.f;            \
    float nr = __shfl_down_sync(FULL, fa.x, 1); if (R27) nr = 0.f;            \
    pr[s][0] = nl;   pr[s][1] = fa.x; pr[s][2] = fa.y; pr[s][3] = fa.z;       \
    pr[s][4] = fa.w; pr[s][5] = fb.x; pr[s][6] = fb.y; pr[s][7] = fb.z;       \
    pr[s][8] = fb.w; pr[s][9] = nr;                                           \
    float lo[10];                                                             \
    _Pragma("unroll")                                                         \
    for (int j = 1; j <= 8; j++) {                                            \
        const float c = fmaxf(pr[s][j], 1e-6f);                               \
        lo[j] = c * __logf(c);                                                \
    }                                                                         \
    lo[0] = __shfl_up_sync(FULL, lo[8], 1);   if (L0)  lo[0] = PL0;           \
    lo[9] = __shfl_down_sync(FULL, lo[1], 1); if (R27) lo[9] = PL0;           \
    _Pragma("unroll")                                                         \
    for (int j = 0; j < 8; j++) hl[s][j] = lo[j] + lo[j + 1] + lo[j + 2];     \
} while (0)

// Emit one output row from ring slots s0,s1,s2; advances oc by one row.
#define OUTPUT(s0, s1, s2) do {                                               \
    float cS1[10], cS2[10];                                                   \
    _Pragma("unroll")                                                         \
    for (int j = 0; j < 10; j++) {                                            \
        cS1[j] = pr[s0][j] + pr[s1][j] + pr[s2][j];                           \
        cS2[j] = fmaf(pr[s0][j], pr[s0][j],                                   \
                 fmaf(pr[s1][j], pr[s1][j], pr[s2][j] * pr[s2][j]));          \
    }                                                                         \
    float m[8], g[8];                                                         \
    _Pragma("unroll")                                                         \
    for (int j = 0; j < 8; j++)                                               \
        m[j] = (cS1[j] + cS1[j + 1] + cS1[j + 2]) * (1.0f / 9.0f);            \
    _Pragma("unroll")                                                         \
    for (int j = 0; j < 8; j++) {                                             \
        const float S2 = cS2[j] + cS2[j + 1] + cS2[j + 2];                    \
        g[j] = fmaxf(S2 * KE, 1e-4f);                                         \
        cS2[j] = fmaf(-9.0f * m[j], m[j], S2);    /* reuse cS2[j] as M2 */    \
    }                                                                         \
    if (act) {                                                                \
        *(float4*)(oc + PLANE)     = make_float4(g[0], g[1], g[2], g[3]);     \
        *(float4*)(oc + PLANE + 4) = make_float4(g[4], g[5], g[6], g[7]);     \
    }                                                                         \
    _Pragma("unroll")                                                         \
    for (int j = 0; j < 8; j++)                                               \
        g[j] = fminf(fmaxf(cS2[j] * KC0, 1e-4f), K1);   /* contrast clamp */  \
    if (act) {                                                                \
        *(float4*)(oc)     = make_float4(g[0], g[1], g[2], g[3]);             \
        *(float4*)(oc + 4) = make_float4(g[4], g[5], g[6], g[7]);             \
    }                                                                         \
    _Pragma("unroll")                                                         \
    for (int j = 0; j < 8; j++)                                               \
        g[j] = fmaxf((hl[s0][j] + hl[s1][j] + hl[s2][j]) * (-KE), 1e-4f);     \
    if (act) {                                                                \
        *(float4*)(oc + 2 * PLANE)     = make_float4(g[0], g[1], g[2], g[3]); \
        *(float4*)(oc + 2 * PLANE + 4) = make_float4(g[4], g[5], g[6], g[7]); \
    }                                                                         \
    _Pragma("unroll")                                                         \
    for (int j = 0; j < 8; j++) {                                             \
        float sad = 0.f;                                                      \
        _Pragma("unroll")                                                     \
        for (int k = 0; k < 3; k++) {                                         \
            sad += fabsf(pr[s0][j + k] - m[j]);                               \
            sad += fabsf(pr[s1][j + k] - m[j]);                               \
            sad += fabsf(pr[s2][j + k] - m[j]);                               \
        }                                                                     \
        g[j] = fmaxf(KH * __frcp_rn(9.0f + sad + 9e-6f), 1e-4f);              \
    }                                                                         \
    if (act) {                                                                \
        *(float4*)(oc + 3 * PLANE)     = make_float4(g[0], g[1], g[2], g[3]); \
        *(float4*)(oc + 3 * PLANE + 4) = make_float4(g[4], g[5], g[6], g[7]); \
    }                                                                         \
    oc += IMG_W;                                                              \
} while (0)

__global__ void __launch_bounds__(128, 6)
medseg10_kernel(const float* __restrict__ x, float* __restrict__ out) {
    const int lane = threadIdx.x & 31;
    const int task = blockIdx.x * 4 + (threadIdx.x >> 5);  // 7168 warp-tasks
    const int plane = task / CHUNKS;
    const int chunk = task - plane * CHUNKS;
    const int ys = chunk * CH;
    const int col = 8 * (lane < 28 ? lane : 27);
    const bool act = (lane < 28);
    const bool L0  = (lane == 0);
    const bool R27 = (lane >= 27);
    const unsigned FULL = 0xFFFFFFFFu;

    const float* __restrict__ base = x + (size_t)plane * PLANE + col;
    float* oc = out + (size_t)plane * 4 * PLANE + (size_t)ys * IMG_W + col;

    float pr[3][10];   // raw 3-row window ring
    float hl[3][8];    // plogp horizontal tri-sums ring
    float4 fa, fb;     // in-flight row

    FETCH(ys - 1); ROWPROC(0);
    FETCH(ys);     ROWPROC(1);
    FETCH(ys + 1);

    #pragma unroll 1
    for (int r = 0; r < 15; r += 3) {
        ROWPROC(2); FETCH(ys + r + 2); OUTPUT(0, 1, 2);
        ROWPROC(0); FETCH(ys + r + 3); OUTPUT(1, 2, 0);
        ROWPROC(1); FETCH(ys + r + 4); OUTPUT(2, 0, 1);
    }
    ROWPROC(2);
    OUTPUT(0, 1, 2);
}

extern "C" void kernel_launch(void* const* d_in, const int* in_sizes, int n_in,
                              void* d_out, int out_size) {
    const float* x = (const float*)d_in[0];
    float* out = (float*)d_out;
    medseg10_kernel<<<7168 / 4, 128>>>(x, out);
}

// round 14
// speedup vs baseline: 1.0824x; 1.0824x over previous
#include <cuda_runtime.h>
#include <cuda_bf16.h>

// MedSegNetV2: 3x3 texture features + martingale — register-rolling march.
// One warp = one full 224-wide row (28 lanes x 8 px), marching down an 8-row
// chunk of one plane. 3-row window in a register ring; no smem, no barriers.
// R14: CH 16->8 (fine-grained tasks kill the wave tail), contrast clamp,
// running output pointer. Proven R12 register regime (occ 5).
// x: [8,64,224,224] f32 -> out: [8,256,224,224] f32, channel = c*4 + feature.

#define IMG_H 224
#define IMG_W 224
#define PLANE (IMG_H * IMG_W)
#define CH 8
#define CHUNKS (IMG_H / CH)       // 28
#define PL0 (-1.3815511e-5f)      // 1e-6 * ln(1e-6)

#define MC   0.6065306597126334f          // exp(-0.5)
#define K1   ((8.0f / 9.0f) * MC)         // contrast ceiling (= value at threshold)
#define KC0  (MC / 9e-6f)                 // contrast tiny-variance slope
#define KE   (MC / 9.0f)
#define KH   (9.0f * MC)

#define FETCH(y) do {                                                         \
    if ((unsigned)(y) < IMG_H) {                                              \
        fa = *(const float4*)(base + (size_t)(y) * IMG_W);                    \
        fb = *(const float4*)(base + (size_t)(y) * IMG_W + 4);                \
    } else {                                                                  \
        fa = make_float4(0.f, 0.f, 0.f, 0.f);                                 \
        fb = make_float4(0.f, 0.f, 0.f, 0.f);                                 \
    }                                                                         \
} while (0)

// Consume fa/fb (one image row) into ring slot s: raw values + plogp tri-sums.
#define ROWPROC(s) do {                                                       \
    float nl = __shfl_up_sync(FULL, fb.w, 1);   if (L0)  nl = 0.f;            \
    float nr = __shfl_down_sync(FULL, fa.x, 1); if (R27) nr = 0.f;            \
    pr[s][0] = nl;   pr[s][1] = fa.x; pr[s][2] = fa.y; pr[s][3] = fa.z;       \
    pr[s][4] = fa.w; pr[s][5] = fb.x; pr[s][6] = fb.y; pr[s][7] = fb.z;       \
    pr[s][8] = fb.w; pr[s][9] = nr;                                           \
    float lo[10];                                                             \
    _Pragma("unroll")                                                         \
    for (int j = 1; j <= 8; j++) {                                            \
        const float c = fmaxf(pr[s][j], 1e-6f);                               \
        lo[j] = c * __logf(c);                                                \
    }                                                                         \
    lo[0] = __shfl_up_sync(FULL, lo[8], 1);   if (L0)  lo[0] = PL0;           \
    lo[9] = __shfl_down_sync(FULL, lo[1], 1); if (R27) lo[9] = PL0;           \
    _Pragma("unroll")                                                         \
    for (int j = 0; j < 8; j++) hl[s][j] = lo[j] + lo[j + 1] + lo[j + 2];     \
} while (0)

// Emit one output row from ring slots s0,s1,s2; advances oc by one row.
#define OUTPUT(s0, s1, s2) do {                                               \
    float cS1[10], cS2[10];                                                   \
    _Pragma("unroll")                                                         \
    for (int j = 0; j < 10; j++) {                                            \
        cS1[j] = pr[s0][j] + pr[s1][j] + pr[s2][j];                           \
        cS2[j] = fmaf(pr[s0][j], pr[s0][j],                                   \
                 fmaf(pr[s1][j], pr[s1][j], pr[s2][j] * pr[s2][j]));          \
    }                                                                         \
    float m[8], g[8];                                                         \
    _Pragma("unroll")                                                         \
    for (int j = 0; j < 8; j++)                                               \
        m[j] = (cS1[j] + cS1[j + 1] + cS1[j + 2]) * (1.0f / 9.0f);            \
    _Pragma("unroll")                                                         \
    for (int j = 0; j < 8; j++) {                                             \
        const float S2 = cS2[j] + cS2[j + 1] + cS2[j + 2];                    \
        g[j] = fmaxf(S2 * KE, 1e-4f);                                         \
        cS2[j] = fmaf(-9.0f * m[j], m[j], S2);    /* reuse cS2[j] as M2 */    \
    }                                                                         \
    if (act) {                                                                \
        *(float4*)(oc + PLANE)     = make_float4(g[0], g[1], g[2], g[3]);     \
        *(float4*)(oc + PLANE + 4) = make_float4(g[4], g[5], g[6], g[7]);     \
    }                                                                         \
    _Pragma("unroll")                                                         \
    for (int j = 0; j < 8; j++)                                               \
        g[j] = fminf(fmaxf(cS2[j] * KC0, 1e-4f), K1);   /* contrast clamp */  \
    if (act) {                                                                \
        *(float4*)(oc)     = make_float4(g[0], g[1], g[2], g[3]);             \
        *(float4*)(oc + 4) = make_float4(g[4], g[5], g[6], g[7]);             \
    }                                                                         \
    _Pragma("unroll")                                                         \
    for (int j = 0; j < 8; j++)                                               \
        g[j] = fmaxf((hl[s0][j] + hl[s1][j] + hl[s2][j]) * (-KE), 1e-4f);     \
    if (act) {                                                                \
        *(float4*)(oc + 2 * PLANE)     = make_float4(g[0], g[1], g[2], g[3]); \
        *(float4*)(oc + 2 * PLANE + 4) = make_float4(g[4], g[5], g[6], g[7]); \
    }                                                                         \
    _Pragma("unroll")                                                         \
    for (int j = 0; j < 8; j++) {                                             \
        float sad = 0.f;                                                      \
        _Pragma("unroll")                                                     \
        for (int k = 0; k < 3; k++) {                                         \
            sad += fabsf(pr[s0][j + k] - m[j]);                               \
            sad += fabsf(pr[s1][j + k] - m[j]);                               \
            sad += fabsf(pr[s2][j + k] - m[j]);                               \
        }                                                                     \
        g[j] = fmaxf(KH * __frcp_rn(9.0f + sad + 9e-6f), 1e-4f);              \
    }                                                                         \
    if (act) {                                                                \
        *(float4*)(oc + 3 * PLANE)     = make_float4(g[0], g[1], g[2], g[3]); \
        *(float4*)(oc + 3 * PLANE + 4) = make_float4(g[4], g[5], g[6], g[7]); \
    }                                                                         \
    oc += IMG_W;                                                              \
} while (0)

__global__ void __launch_bounds__(128, 5)
medseg11_kernel(const float* __restrict__ x, float* __restrict__ out) {
    const int lane = threadIdx.x & 31;
    const int task = blockIdx.x * 4 + (threadIdx.x >> 5);  // 14336 warp-tasks
    const int plane = task / CHUNKS;
    const int chunk = task - plane * CHUNKS;
    const int ys = chunk * CH;
    const int col = 8 * (lane < 28 ? lane : 27);
    const bool act = (lane < 28);
    const bool L0  = (lane == 0);
    const bool R27 = (lane >= 27);
    const unsigned FULL = 0xFFFFFFFFu;

    const float* __restrict__ base = x + (size_t)plane * PLANE + col;
    float* oc = out + (size_t)plane * 4 * PLANE + (size_t)ys * IMG_W + col;

    float pr[3][10];   // raw 3-row window ring
    float hl[3][8];    // plogp horizontal tri-sums ring
    float4 fa, fb;     // in-flight row

    // Prolog: rows ys-1, ys into slots 0,1; prefetch row ys+1.
    FETCH(ys - 1); ROWPROC(0);
    FETCH(ys);     ROWPROC(1);
    FETCH(ys + 1);

    // 8 output rows: 2 triple-steps + 2-step epilog.
    #pragma unroll 1
    for (int r = 0; r < 6; r += 3) {
        ROWPROC(2); FETCH(ys + r + 2); OUTPUT(0, 1, 2);
        ROWPROC(0); FETCH(ys + r + 3); OUTPUT(1, 2, 0);
        ROWPROC(1); FETCH(ys + r + 4); OUTPUT(2, 0, 1);
    }
    ROWPROC(2); FETCH(ys + 8); OUTPUT(0, 1, 2);
    ROWPROC(0);                OUTPUT(1, 2, 0);
}

extern "C" void kernel_launch(void* const* d_in, const int* in_sizes, int n_in,
                              void* d_out, int out_size) {
    const float* x = (const float*)d_in[0];
    float* out = (float*)d_out;
    // 512 planes x 28 chunks = 14336 warp-tasks; 4 warps per 128-thread block.
    medseg11_kernel<<<14336 / 4, 128>>>(x, out);
}